// round 3
// baseline (speedup 1.0000x reference)
#include <cuda_runtime.h>
#include <math.h>

typedef unsigned long long ull;

#define B_   64
#define H_   1024
#define I_   512
#define L_   4
#define S_   512
#define H4   4096
#define KT   32
#define NCTA 128     // 4 layers * 32 CTAs
#define NTHR 256

// Hidden state double-buffered by wave parity: [parity][layer][row*H + col]
__device__ float g_h[2][L_][B_ * H_];
__device__ unsigned g_bar_count;
__device__ volatile unsigned g_bar_gen;

__device__ __forceinline__ ull bcast2(float v) {
    ull r; asm("mov.b64 %0, {%1, %1};" : "=l"(r) : "f"(v)); return r;
}
__device__ __forceinline__ void fma2(ull& d, ull a, ull b) {
    asm("fma.rn.f32x2 %0, %1, %2, %0;" : "+l"(d) : "l"(a), "l"(b));
}
__device__ __forceinline__ float2 u2f(ull v) {
    float2 f; asm("mov.b64 {%0, %1}, %2;" : "=f"(f.x), "=f"(f.y) : "l"(v)); return f;
}

__device__ __forceinline__ void grid_sync() {
    __syncthreads();
    if (threadIdx.x == 0) {
        __threadfence();
        unsigned gen = g_bar_gen;
        if (atomicAdd(&g_bar_count, 1u) == NCTA - 1u) {
            g_bar_count = 0;
            __threadfence();
            g_bar_gen = gen + 1u;
        } else {
            while (g_bar_gen == gen) __nanosleep(64);
        }
        __threadfence();
    }
    __syncthreads();
}

// acc[rowpair][gate] += inp[64 x K] @ W[K x 4096], this CTA's 32 hcols x 4 gates.
// inp row-major, leading dim ldi. Swizzled SMEM staging, register prefetch.
// USE_CG: bypass L1 (required for h buffers, which are rewritten every 2 waves).
template<bool USE_CG>
__device__ __forceinline__ void gemm_part(
    const float* __restrict__ inp, int ldi, int K,
    const float* __restrict__ W, int hc0,
    float* sm_inp, float4* sm_w, ull acc[4][4])
{
    const int t    = threadIdx.x;
    const int lane = t & 31;
    const int r    = t >> 5;
    const int ntiles = K / KT;
    const int r2   = 2 * r;

    float pa[8];
    float pw[4][4];
    #pragma unroll
    for (int i = 0; i < 8; i++) {
        const float* p = inp + (size_t)(r + 8 * i) * ldi + lane;
        pa[i] = USE_CG ? __ldcg(p) : __ldg(p);
    }
    #pragma unroll
    for (int j = 0; j < 4; j++)
        #pragma unroll
        for (int g = 0; g < 4; g++)
            pw[j][g] = __ldg(W + (size_t)(r + 8 * j) * H4 + g * 1024 + hc0 + lane);

    for (int tile = 0; tile < ntiles; tile++) {
        __syncthreads();
        #pragma unroll
        for (int i = 0; i < 8; i++) {
            int row = r + 8 * i;
            sm_inp[lane * 64 + ((((row >> 2) ^ (lane & 15)) << 2) | (row & 3))] = pa[i];
        }
        #pragma unroll
        for (int j = 0; j < 4; j++)
            sm_w[(r + 8 * j) * 32 + lane] =
                make_float4(pw[j][0], pw[j][1], pw[j][2], pw[j][3]);

        if (tile + 1 < ntiles) {
            const int k0 = (tile + 1) * KT;
            #pragma unroll
            for (int i = 0; i < 8; i++) {
                const float* p = inp + (size_t)(r + 8 * i) * ldi + k0 + lane;
                pa[i] = USE_CG ? __ldcg(p) : __ldg(p);
            }
            #pragma unroll
            for (int j = 0; j < 4; j++)
                #pragma unroll
                for (int g = 0; g < 4; g++)
                    pw[j][g] = __ldg(W + (size_t)(k0 + r + 8 * j) * H4 + g * 1024 + hc0 + lane);
        }
        __syncthreads();

        #pragma unroll
        for (int kk = 0; kk < KT; kk++) {
            float4 wv = sm_w[kk * 32 + lane];
            ull w0 = bcast2(wv.x), w1 = bcast2(wv.y), w2 = bcast2(wv.z), w3 = bcast2(wv.w);
            const float* base = sm_inp + kk * 64;
            const int g0 = (r2 ^ (kk & 15)) << 2;
            const int g1 = ((r2 + 1) ^ (kk & 15)) << 2;
            ull p0 = *(const ull*)(base + g0);
            ull p1 = *(const ull*)(base + g0 + 2);
            ull q0 = *(const ull*)(base + g1);
            ull q1 = *(const ull*)(base + g1 + 2);
            fma2(acc[0][0], p0, w0); fma2(acc[0][1], p0, w1);
            fma2(acc[0][2], p0, w2); fma2(acc[0][3], p0, w3);
            fma2(acc[1][0], p1, w0); fma2(acc[1][1], p1, w1);
            fma2(acc[1][2], p1, w2); fma2(acc[1][3], p1, w3);
            fma2(acc[2][0], q0, w0); fma2(acc[2][1], q0, w1);
            fma2(acc[2][2], q0, w2); fma2(acc[2][3], q0, w3);
            fma2(acc[3][0], q1, w0); fma2(acc[3][1], q1, w1);
            fma2(acc[3][2], q1, w2); fma2(acc[3][3], q1, w3);
        }
    }
}

__global__ void __launch_bounds__(NTHR, 1)
lstm_persist(const float* __restrict__ x,
             const float* __restrict__ Wx0, const float* __restrict__ Wh0,
             const float* __restrict__ b0,
             const float* __restrict__ Wxr, const float* __restrict__ Whr,
             const float* __restrict__ br,
             float* __restrict__ out)
{
    __shared__ float  sm_inp[KT * 64];
    __shared__ float4 sm_w[KT * 32];

    const int layer = blockIdx.x >> 5;
    const int hc0   = (blockIdx.x & 31) * 32;
    const int t     = threadIdx.x;
    const int lane  = t & 31;
    const int r     = t >> 5;
    const int hcol  = hc0 + lane;

    const float* WA   = (layer == 0) ? Wx0 : Wxr + (size_t)(layer - 1) * H_ * H4;
    const float* WB   = (layer == 0) ? Wh0 : Whr + (size_t)(layer - 1) * H_ * H4;
    const float* bias = (layer == 0) ? b0  : br + (size_t)(layer - 1) * H4;
    const int    KA   = (layer == 0) ? I_  : H_;

    float b4[4];
    #pragma unroll
    for (int g = 0; g < 4; g++)
        b4[g] = __ldg(bias + g * 1024 + hcol);

    float creg[8];
    #pragma unroll
    for (int i = 0; i < 8; i++) creg[i] = 0.f;

    const size_t HS = (size_t)S_ * B_ * H_;
    const size_t BH = (size_t)B_ * H_;

    for (int w = 0; w < S_ + L_ - 1; w++) {
        const int s = w - layer;
        if (s >= 0 && s < S_) {
            const int prPrev = (w & 1) ^ 1;   // parity written at wave w-1
            const int prCur  = w & 1;

            ull acc[4][4];
            #pragma unroll
            for (int p = 0; p < 4; p++)
                #pragma unroll
                for (int g = 0; g < 4; g++)
                    acc[p][g] = bcast2(b4[g]);

            if (layer == 0) {
                gemm_part<false>(x + (size_t)s * B_ * I_, I_, KA, WA, hc0,
                                 sm_inp, sm_w, acc);
            } else {
                gemm_part<true>(&g_h[prPrev][layer - 1][0], H_, KA, WA, hc0,
                                sm_inp, sm_w, acc);
            }
            gemm_part<true>(&g_h[prPrev][layer][0], H_, H_, WB, hc0,
                            sm_inp, sm_w, acc);

            float* hw = &g_h[prCur][layer][0];
            #pragma unroll
            for (int p = 0; p < 4; p++) {
                float2 zi = u2f(acc[p][0]);
                float2 zf = u2f(acc[p][1]);
                float2 zg = u2f(acc[p][2]);
                float2 zo = u2f(acc[p][3]);
                #pragma unroll
                for (int half = 0; half < 2; half++) {
                    const float vi = half ? zi.y : zi.x;
                    const float vf = half ? zf.y : zf.x;
                    const float vg = half ? zg.y : zg.x;
                    const float vo = half ? zo.y : zo.x;
                    const int rr  = p * 2 + half;
                    const int row = r * 8 + rr;
                    const float ig = 1.f / (1.f + expf(-vi));
                    const float fg = 1.f / (1.f + expf(-vf));
                    const float og = 1.f / (1.f + expf(-vo));
                    const float cn = fg * creg[rr] + ig * tanhf(vg);
                    const float hn = og * tanhf(cn);
                    creg[rr] = cn;
                    hw[row * H_ + hcol] = hn;
                    if (layer == L_ - 1)
                        out[(size_t)s * BH + row * H_ + hcol] = hn;
                    if (s == S_ - 1) {
                        out[HS + (size_t)layer * BH + row * H_ + hcol] = hn;
                        out[HS + (size_t)L_ * BH + (size_t)layer * BH + row * H_ + hcol] = cn;
                    }
                }
            }
        }
        if (w < S_ + L_ - 2) grid_sync();
    }
}

extern "C" void kernel_launch(void* const* d_in, const int* in_sizes, int n_in,
                              void* d_out, int out_size)
{
    const float* x   = (const float*)d_in[0];   // [512, 64, 512]
    const float* Wx0 = (const float*)d_in[1];   // [512, 4096]
    const float* Wh0 = (const float*)d_in[2];   // [1024, 4096]
    const float* b0  = (const float*)d_in[3];   // [4096]
    const float* Wxr = (const float*)d_in[4];   // [3, 1024, 4096]
    const float* Whr = (const float*)d_in[5];   // [3, 1024, 4096]
    const float* br  = (const float*)d_in[6];   // [3, 4096]
    float* out = (float*)d_out;

    void* hp;
    cudaGetSymbolAddress(&hp, g_h);
    cudaMemsetAsync(hp, 0, sizeof(float) * 2 * L_ * B_ * H_, 0);

    lstm_persist<<<NCTA, NTHR>>>(x, Wx0, Wh0, b0, Wxr, Whr, br, out);
}